// round 5
// baseline (speedup 1.0000x reference)
#include <cuda_runtime.h>
#include <cuda_bf16.h>
#include <math.h>

#define NCL 10
#define DD 64
#define TPB1 512

typedef unsigned long long ull;

// final cluster centers from the iterative kernel
__device__ float g_cc[NCL * DD];

// ---------------- packed f32x2 helpers ----------------

__device__ __forceinline__ ull fma2(ull a, ull b, ull c) {
    ull d;
    asm("fma.rn.f32x2 %0, %1, %2, %3;" : "=l"(d) : "l"(a), "l"(b), "l"(c));
    return d;
}
__device__ __forceinline__ ull add2(ull a, ull b) {
    ull d;
    asm("add.rn.f32x2 %0, %1, %2;" : "=l"(d) : "l"(a), "l"(b));
    return d;
}
__device__ __forceinline__ float hsum2(ull v) {
    return __uint_as_float((unsigned)v) + __uint_as_float((unsigned)(v >> 32));
}
__device__ __forceinline__ float fast_sigmoid(float x) {
    return 1.f / (1.f + __expf(-x));
}
__device__ __forceinline__ float fast_tanh(float x) {
    return 1.f - 2.f / (1.f + __expf(2.f * x));   // stable at both tails
}

// ---------------- staging helpers ----------------

__device__ __forceinline__ void cp_async16(float* smem_dst, const float* gsrc) {
    unsigned d = (unsigned)__cvta_generic_to_shared(smem_dst);
    asm volatile("cp.async.cg.shared.global [%0], [%1], 16;\n" :: "r"(d), "l"(gsrc));
}

// XOR swizzle: (r, c) -> r*L + (c ^ ((r<<2) & (L-4))). float4-preserving,
// conflict-free LDS.128 when lanes read consecutive rows.
__device__ __forceinline__ void stage_w(const float* __restrict__ g, float* __restrict__ s,
                                        int R, int L, int tid, int T) {
    int total4 = (R * L) >> 2;
    for (int e4 = tid; e4 < total4; e4 += T) {
        int e = e4 << 2;
        int r = e / L;
        int c = e & (L - 1);
        float4 v = *reinterpret_cast<const float4*>(g + e);
        *reinterpret_cast<float4*>(s + r * L + (c ^ ((r << 2) & (L - 4)))) = v;
    }
}

__device__ __forceinline__ void stage_w_async(const float* __restrict__ g, float* __restrict__ s,
                                              int R, int L, int tid, int T) {
    int total4 = (R * L) >> 2;
    for (int e4 = tid; e4 < total4; e4 += T) {
        int e = e4 << 2;
        int r = e / L;
        int c = e & (L - 1);
        cp_async16(s + r * L + (c ^ ((r << 2) & (L - 4))), g + e);
    }
}

// packed gemm: acc2[n] accumulates (pairwise) sum_c W[r][c]*act[n*L+c]
// over cols [c0, c0+nc). Weight LDS amortized over 10 clusters; act LDS are
// warp broadcasts. FFMA2 halves FMA instruction count.
__device__ __forceinline__ void gemm10p(const float* __restrict__ Wsm,
                                        const float* __restrict__ act,
                                        int r, int L, int c0, int nc, ull* acc2) {
#pragma unroll
    for (int n = 0; n < NCL; n++) acc2[n] = 0ull;
    const int sw = (r << 2) & (L - 4);
    const float* wrow = Wsm + r * L;
#pragma unroll 4
    for (int c = c0; c < c0 + nc; c += 4) {
        ulonglong2 w = *reinterpret_cast<const ulonglong2*>(wrow + (c ^ sw));
#pragma unroll
        for (int n = 0; n < NCL; n++) {
            ulonglong2 a = *reinterpret_cast<const ulonglong2*>(act + n * L + c);
            acc2[n] = fma2(w.x, a.x, acc2[n]);
            acc2[n] = fma2(w.y, a.y, acc2[n]);
        }
    }
}

// ---------------- kernel 1: iterative slot attention (1 block, 512 thr) ----------------

__global__ void __launch_bounds__(TPB1) iter_kernel(
    const float* __restrict__ cc0,
    const float* __restrict__ Wk, const float* __restrict__ bk,
    const float* __restrict__ Wq, const float* __restrict__ bq,
    const float* __restrict__ Wv, const float* __restrict__ bv,
    const float* __restrict__ ccg, const float* __restrict__ ccb,
    const float* __restrict__ Wih, const float* __restrict__ Whh,
    const float* __restrict__ bih, const float* __restrict__ bhh,
    const float* __restrict__ g_lng, const float* __restrict__ g_lnb,
    const float* __restrict__ W1, const float* __restrict__ b1,
    const float* __restrict__ W2, const float* __restrict__ b2)
{
    extern __shared__ float sm[];
    float* Wq_s   = sm;                 // 4096
    float* Wih_s  = Wq_s + 4096;        // 12288
    float* Whh_s  = Wih_s + 12288;      // 12288
    float* W1_s   = Whh_s + 12288;      // 8192 (Wk during init)
    float* W2_s   = W1_s + 8192;        // 8192 (Wv during init)
    float* cc_s   = W2_s + 8192;        // 640
    float* ccp_s  = cc_s + 640;         // 640
    float* kk_s   = ccp_s + 640;        // 640
    float* lnx_s  = kk_s + 640;         // 640
    float* q_s    = lnx_s + 640;        // 640
    float* VW_s   = q_s + 640;          // 1920 ([m][192])
    float* gh_s   = VW_s + 1920;        // 1920 ([n][192])
    float* hh_s   = gh_s + 1920;        // 1280 ([n][128]); aliases vv during init
    float* attn_s = hh_s + 1280;        // 112 (100 used)
    float* mv_s   = attn_s + 112;       // 32 (20 used)
    float* vv_s   = hh_s;               // alias

    const int tid  = threadIdx.x;
    const int lane = tid & 31;
    const int wid  = tid >> 5;

    // async stage of the big iteration weights (group 0)
    stage_w_async(Wih, Wih_s, 192, 64, tid, TPB1);
    stage_w_async(Whh, Whh_s, 192, 64, tid, TPB1);
    asm volatile("cp.async.commit_group;\n" ::: "memory");

    // sync stage of the small init weights + cc
    stage_w(Wq, Wq_s, 64, 64, tid, TPB1);
    stage_w(Wk, W1_s, 64, 64, tid, TPB1);
    stage_w(Wv, W2_s, 64, 64, tid, TPB1);
    if (tid < 160) *reinterpret_cast<float4*>(cc_s + tid * 4) =
        *reinterpret_cast<const float4*>(cc0 + tid * 4);
    __syncthreads();

    // k, v : 128 rows x splitk4 (16 cols each), shuffle-combine in lane quads
    {
        int rid = tid >> 2, kp = tid & 3;
        ull acc2[NCL];
        const float* Wm = (rid < 64) ? W1_s : W2_s;
        int row = (rid < 64) ? rid : rid - 64;
        gemm10p(Wm, cc_s, row, 64, kp * 16, 16, acc2);
#pragma unroll
        for (int n = 0; n < NCL; n++) {
            acc2[n] = add2(acc2[n], __shfl_xor_sync(0xffffffffu, acc2[n], 1));
            acc2[n] = add2(acc2[n], __shfl_xor_sync(0xffffffffu, acc2[n], 2));
        }
        if (kp == 0) {
            float b = (rid < 64) ? bk[row] : bv[row];
            float* dst = (rid < 64) ? kk_s : vv_s;
#pragma unroll
            for (int n = 0; n < NCL; n++) dst[n * 64 + row] = hsum2(acc2[n]) + b;
        }
    }
    __syncthreads();

    // stage W1/W2 async (group 1) — overwrites Wk/Wv areas (already consumed)
    stage_w_async(W1, W1_s, 128, 64, tid, TPB1);
    stage_w_async(W2, W2_s, 64, 128, tid, TPB1);
    asm volatile("cp.async.commit_group;\n" ::: "memory");
    asm volatile("cp.async.wait_group 1;\n" ::: "memory");  // Wih/Whh ready
    __syncthreads();

    // VW[m][r] = v[m] . Wih[r]  (iteration-invariant hoist), 192 rows x splitk2
    if (tid < 384) {
        int rid = tid >> 1, kp = tid & 1;
        ull acc2[NCL];
        gemm10p(Wih_s, vv_s, rid, 64, kp * 32, 32, acc2);
#pragma unroll
        for (int n = 0; n < NCL; n++)
            acc2[n] = add2(acc2[n], __shfl_xor_sync(0xffffffffu, acc2[n], 1));
        if (kp == 0) {
#pragma unroll
            for (int n = 0; n < NCL; n++) VW_s[n * 192 + rid] = hsum2(acc2[n]);
        }
    }
    asm volatile("cp.async.wait_group 0;\n" ::: "memory");  // W1/W2 ready
    __syncthreads();

    for (int it = 0; it < 3; ++it) {
        // ccp copy + LN1 stats (warp-per-row)
        ccp_s[tid] = cc_s[tid];
        if (tid < 128) ccp_s[512 + tid] = cc_s[512 + tid];
        if (wid < NCL) {
            float x0 = cc_s[wid * 64 + lane * 2];
            float x1 = cc_s[wid * 64 + lane * 2 + 1];
            float s = x0 + x1, q2 = x0 * x0 + x1 * x1;
#pragma unroll
            for (int o = 16; o; o >>= 1) {
                s  += __shfl_xor_sync(0xffffffffu, s, o);
                q2 += __shfl_xor_sync(0xffffffffu, q2, o);
            }
            if (lane == 0) {
                float m = s * (1.f / 64.f);
                mv_s[2 * wid] = m;
                mv_s[2 * wid + 1] = rsqrtf(q2 * (1.f / 64.f) - m * m + 1e-5f);
            }
        }
        __syncthreads();
        {
            int e = tid, n = e >> 6, i = e & 63;
            lnx_s[e] = (cc_s[e] - mv_s[2 * n]) * mv_s[2 * n + 1] * ccg[i] + ccb[i];
            if (tid < 128) {
                e = 512 + tid; n = e >> 6; i = e & 63;
                lnx_s[e] = (cc_s[e] - mv_s[2 * n]) * mv_s[2 * n + 1] * ccg[i] + ccb[i];
            }
        }
        __syncthreads();

        // stage A: 256 rows (q: 0-63 from lnx/Wq, gh: 64-255 from ccp/Whh) x splitk2
        {
            int rid = tid >> 1, kp = tid & 1;
            ull acc2[NCL];
            if (rid < 64) gemm10p(Wq_s, lnx_s, rid, 64, kp * 32, 32, acc2);
            else          gemm10p(Whh_s, ccp_s, rid - 64, 64, kp * 32, 32, acc2);
#pragma unroll
            for (int n = 0; n < NCL; n++)
                acc2[n] = add2(acc2[n], __shfl_xor_sync(0xffffffffu, acc2[n], 1));
            if (kp == 0) {
                if (rid < 64) {
                    float b = bq[rid];
#pragma unroll
                    for (int n = 0; n < NCL; n++) q_s[n * 64 + rid] = hsum2(acc2[n]) + b;
                } else {
                    int r = rid - 64;
                    float b = bhh[r];
#pragma unroll
                    for (int n = 0; n < NCL; n++) gh_s[n * 192 + r] = hsum2(acc2[n]) + b;
                }
            }
        }
        __syncthreads();

        // logits: 100 dots x splitk4 (all threads compute w/ clamp, 400 write-eligible)
        {
            int nm = tid >> 2; if (nm > 99) nm = 99;
            int kp = tid & 3;
            int n = nm / 10, m = nm % 10;
            float s = 0.f;
            int c0 = kp * 16;
#pragma unroll
            for (int j = 0; j < 16; j++)
                s = fmaf(kk_s[n * 64 + c0 + j], q_s[m * 64 + c0 + j], s);
            s += __shfl_xor_sync(0xffffffffu, s, 1);
            s += __shfl_xor_sync(0xffffffffu, s, 2);
            if (tid < 400 && kp == 0) attn_s[n * 10 + m] = s * 0.125f;
        }
        __syncthreads();
        // softmax over axis 0 (+EPS)
        if (tid < NCL) {
            int m = tid;
            float a[NCL], mx = -1e30f;
#pragma unroll
            for (int n = 0; n < NCL; n++) { a[n] = attn_s[n * 10 + m]; mx = fmaxf(mx, a[n]); }
            float ss = 0.f;
#pragma unroll
            for (int n = 0; n < NCL; n++) { a[n] = __expf(a[n] - mx); ss += a[n]; }
            float inv = 1.f / ss;
#pragma unroll
            for (int n = 0; n < NCL; n++) attn_s[n * 10 + m] = a[n] * inv + 1e-8f;
        }
        __syncthreads();
        // renormalize over axis -1
        if (tid < NCL) {
            int n = tid;
            float ss = 0.f;
#pragma unroll
            for (int m = 0; m < NCL; m++) ss += attn_s[n * 10 + m];
            float inv = 1.f / ss;
#pragma unroll
            for (int m = 0; m < NCL; m++) attn_s[n * 10 + m] *= inv;
        }
        __syncthreads();

        // GRU (gi = attn @ VW + b_ih; gh precomputed)
        for (int e = tid; e < 640; e += TPB1) {
            int n = e >> 6, i = e & 63;
            float gi0 = bih[i], gi1 = bih[64 + i], gi2 = bih[128 + i];
#pragma unroll
            for (int m = 0; m < NCL; m++) {
                float a = attn_s[n * 10 + m];
                const float* vw = VW_s + m * 192;
                gi0 = fmaf(a, vw[i], gi0);
                gi1 = fmaf(a, vw[64 + i], gi1);
                gi2 = fmaf(a, vw[128 + i], gi2);
            }
            float h0 = gh_s[n * 192 + i];
            float h1 = gh_s[n * 192 + 64 + i];
            float h2 = gh_s[n * 192 + 128 + i];
            float r = fast_sigmoid(gi0 + h0);
            float z = fast_sigmoid(gi1 + h1);
            float nn = fast_tanh(gi2 + r * h2);
            cc_s[e] = (1.f - z) * nn + z * ccp_s[e];
        }
        __syncthreads();

        // LN2 stats + lnx
        if (wid < NCL) {
            float x0 = cc_s[wid * 64 + lane * 2];
            float x1 = cc_s[wid * 64 + lane * 2 + 1];
            float s = x0 + x1, q2 = x0 * x0 + x1 * x1;
#pragma unroll
            for (int o = 16; o; o >>= 1) {
                s  += __shfl_xor_sync(0xffffffffu, s, o);
                q2 += __shfl_xor_sync(0xffffffffu, q2, o);
            }
            if (lane == 0) {
                float m = s * (1.f / 64.f);
                mv_s[2 * wid] = m;
                mv_s[2 * wid + 1] = rsqrtf(q2 * (1.f / 64.f) - m * m + 1e-5f);
            }
        }
        __syncthreads();
        {
            int e = tid, n = e >> 6, i = e & 63;
            lnx_s[e] = (cc_s[e] - mv_s[2 * n]) * mv_s[2 * n + 1] * g_lng[i] + g_lnb[i];
            if (tid < 128) {
                e = 512 + tid; n = e >> 6; i = e & 63;
                lnx_s[e] = (cc_s[e] - mv_s[2 * n]) * mv_s[2 * n + 1] * g_lng[i] + g_lnb[i];
            }
        }
        __syncthreads();

        // MLP1: 128 rows x splitk4
        {
            int rid = tid >> 2, kp = tid & 3;
            ull acc2[NCL];
            gemm10p(W1_s, lnx_s, rid, 64, kp * 16, 16, acc2);
#pragma unroll
            for (int n = 0; n < NCL; n++) {
                acc2[n] = add2(acc2[n], __shfl_xor_sync(0xffffffffu, acc2[n], 1));
                acc2[n] = add2(acc2[n], __shfl_xor_sync(0xffffffffu, acc2[n], 2));
            }
            if (kp == 0) {
                float b = b1[rid];
#pragma unroll
                for (int n = 0; n < NCL; n++)
                    hh_s[n * 128 + rid] = fmaxf(hsum2(acc2[n]) + b, 0.f);
            }
        }
        __syncthreads();
        // MLP2 + residual: 64 rows (L=128) x splitk8
        {
            int rid = tid >> 3, kp = tid & 7;
            ull acc2[NCL];
            gemm10p(W2_s, hh_s, rid, 128, kp * 16, 16, acc2);
#pragma unroll
            for (int n = 0; n < NCL; n++) {
                acc2[n] = add2(acc2[n], __shfl_xor_sync(0xffffffffu, acc2[n], 1));
                acc2[n] = add2(acc2[n], __shfl_xor_sync(0xffffffffu, acc2[n], 2));
                acc2[n] = add2(acc2[n], __shfl_xor_sync(0xffffffffu, acc2[n], 4));
            }
            if (kp == 0) {
                float b = b2[rid];
#pragma unroll
                for (int n = 0; n < NCL; n++)
                    cc_s[n * 64 + rid] += hsum2(acc2[n]) + b;
            }
        }
        __syncthreads();
    }

    // write ALL 640 elements (R2 bug: only first 512 were written)
    g_cc[tid] = cc_s[tid];
    if (tid < 128) g_cc[512 + tid] = cc_s[512 + tid];
}

// ---------------- kernel 2: per-slot MLP + max (4096 blocks) ----------------

__global__ void __launch_bounds__(64) slot_kernel(
    const float* __restrict__ Wa, const float* __restrict__ ba,
    const float* __restrict__ Wb, const float* __restrict__ bb,
    float* __restrict__ out)
{
    __shared__ float bufA[4096];
    __shared__ float bufB[4096];
    __shared__ float cc2[640];
    __shared__ float hsm[640];

    const int s = blockIdx.x;
    const int t = threadIdx.x;
    const float* wa = Wa + (size_t)s * 4096;
    const float* wb = Wb + (size_t)s * 4096;

    // double-buffered streaming loads (swizzled dst), Wb in flight during phase 1
#pragma unroll
    for (int k = 0; k < 16; ++k) {
        int e = (t + 64 * k) * 4;
        int r = e >> 6, c = e & 63;
        cp_async16(&bufA[r * 64 + (c ^ ((r << 2) & 60))], wa + e);
    }
    asm volatile("cp.async.commit_group;\n" ::: "memory");
#pragma unroll
    for (int k = 0; k < 16; ++k) {
        int e = (t + 64 * k) * 4;
        int r = e >> 6, c = e & 63;
        cp_async16(&bufB[r * 64 + (c ^ ((r << 2) & 60))], wb + e);
    }
    asm volatile("cp.async.commit_group;\n" ::: "memory");

    for (int e = t; e < 640; e += 64) cc2[e] = g_cc[e];

    asm volatile("cp.async.wait_group 1;\n" ::: "memory");
    __syncthreads();

    ull acc2[NCL];
    // h[n][t] = relu(Wa[t] . cc[n] + ba[s][t])
    gemm10p(bufA, cc2, t, 64, 0, 64, acc2);
    {
        float b = ba[s * 64 + t];
#pragma unroll
        for (int n = 0; n < NCL; n++) hsm[n * 64 + t] = fmaxf(hsum2(acc2[n]) + b, 0.f);
    }

    asm volatile("cp.async.wait_group 0;\n" ::: "memory");
    __syncthreads();

    // out[n][t] = Wb[t] . h[n] + bb[s][t]; max over n
    gemm10p(bufB, hsm, t, 64, 0, 64, acc2);
    float b = bb[s * 64 + t];
    float m = -3.4e38f;
#pragma unroll
    for (int n = 0; n < NCL; n++) m = fmaxf(m, hsum2(acc2[n]) + b);
    out[s * 64 + t] = m;
}

// ---------------- launch ----------------

extern "C" void kernel_launch(void* const* d_in, const int* in_sizes, int n_in,
                              void* d_out, int out_size) {
    const float* cc0 = (const float*)d_in[0];
    const float* Wk  = (const float*)d_in[1];
    const float* bk  = (const float*)d_in[2];
    const float* Wq  = (const float*)d_in[3];
    const float* bq  = (const float*)d_in[4];
    const float* Wv  = (const float*)d_in[5];
    const float* bv  = (const float*)d_in[6];
    const float* ccg = (const float*)d_in[7];
    const float* ccb = (const float*)d_in[8];
    const float* Wih = (const float*)d_in[9];
    const float* Whh = (const float*)d_in[10];
    const float* bih = (const float*)d_in[11];
    const float* bhh = (const float*)d_in[12];
    const float* lng = (const float*)d_in[13];
    const float* lnb = (const float*)d_in[14];
    const float* W1  = (const float*)d_in[15];
    const float* b1  = (const float*)d_in[16];
    const float* W2  = (const float*)d_in[17];
    const float* b2  = (const float*)d_in[18];
    const float* Wa  = (const float*)d_in[19];
    const float* ba  = (const float*)d_in[20];
    const float* Wb  = (const float*)d_in[21];
    const float* bb  = (const float*)d_in[22];
    float* out = (float*)d_out;

    constexpr int SMEM1 = 53520 * 4;  // 214,080 B < 227 KB opt-in
    cudaFuncSetAttribute(iter_kernel, cudaFuncAttributeMaxDynamicSharedMemorySize, SMEM1);

    iter_kernel<<<1, TPB1, SMEM1>>>(cc0, Wk, bk, Wq, bq, Wv, bv, ccg, ccb,
                                    Wih, Whh, bih, bhh, lng, lnb, W1, b1, W2, b2);
    slot_kernel<<<4096, 64>>>(Wa, ba, Wb, bb, out);
}

// round 6
// speedup vs baseline: 1.5277x; 1.5277x over previous
#include <cuda_runtime.h>
#include <cuda_bf16.h>
#include <math.h>

#define NCL 10
#define DD 64
#define TPB1 512

// final cluster centers from the iterative kernel
__device__ float g_cc[NCL * DD];

// ---------------- helpers ----------------

__device__ __forceinline__ float fast_sigmoid(float x) {
    return 1.f / (1.f + __expf(-x));
}
__device__ __forceinline__ float fast_tanh(float x) {
    return 1.f - 2.f / (1.f + __expf(2.f * x));   // stable at both tails
}

__device__ __forceinline__ void cp_async16(float* smem_dst, const float* gsrc) {
    unsigned d = (unsigned)__cvta_generic_to_shared(smem_dst);
    asm volatile("cp.async.cg.shared.global [%0], [%1], 16;\n" :: "r"(d), "l"(gsrc));
}

// XOR swizzle: (r, c) -> r*L + (c ^ ((r<<2) & (L-4))). float4-preserving,
// conflict-free LDS.128 when lanes read consecutive rows.
__device__ __forceinline__ void stage_w(const float* __restrict__ g, float* __restrict__ s,
                                        int R, int L, int tid, int T) {
    int total4 = (R * L) >> 2;
    for (int e4 = tid; e4 < total4; e4 += T) {
        int e = e4 << 2;
        int r = e / L;
        int c = e & (L - 1);
        float4 v = *reinterpret_cast<const float4*>(g + e);
        *reinterpret_cast<float4*>(s + r * L + (c ^ ((r << 2) & (L - 4)))) = v;
    }
}

__device__ __forceinline__ void stage_w_async(const float* __restrict__ g, float* __restrict__ s,
                                              int R, int L, int tid, int T) {
    int total4 = (R * L) >> 2;
    for (int e4 = tid; e4 < total4; e4 += T) {
        int e = e4 << 2;
        int r = e / L;
        int c = e & (L - 1);
        cp_async16(s + r * L + (c ^ ((r << 2) & (L - 4))), g + e);
    }
}

// scalar gemm over a column subrange: acc[n] = sum_{c in [c0,c0+nc)} W[r][c]*act[n*L+c]
// One weight LDS.128 feeds 40 FFMAs; act reads are warp broadcasts.
__device__ __forceinline__ void gemm_sc(const float* __restrict__ Wsm,
                                        const float* __restrict__ act,
                                        int r, int L, int c0, int nc, float* acc) {
#pragma unroll
    for (int n = 0; n < NCL; n++) acc[n] = 0.f;
    const int sw = (r << 2) & (L - 4);
    const float* wrow = Wsm + r * L;
#pragma unroll 4
    for (int c = c0; c < c0 + nc; c += 4) {
        float4 w = *reinterpret_cast<const float4*>(wrow + (c ^ sw));
#pragma unroll
        for (int n = 0; n < NCL; n++) {
            float4 a = *reinterpret_cast<const float4*>(act + n * L + c);
            acc[n] = fmaf(w.x, a.x, acc[n]);
            acc[n] = fmaf(w.y, a.y, acc[n]);
            acc[n] = fmaf(w.z, a.z, acc[n]);
            acc[n] = fmaf(w.w, a.w, acc[n]);
        }
    }
}

// ---------------- kernel 1: iterative slot attention (1 block, 512 thr) ----------------

__global__ void __launch_bounds__(TPB1) iter_kernel(
    const float* __restrict__ cc0,
    const float* __restrict__ Wk, const float* __restrict__ bk,
    const float* __restrict__ Wq, const float* __restrict__ bq,
    const float* __restrict__ Wv, const float* __restrict__ bv,
    const float* __restrict__ ccg, const float* __restrict__ ccb,
    const float* __restrict__ Wih, const float* __restrict__ Whh,
    const float* __restrict__ bih, const float* __restrict__ bhh,
    const float* __restrict__ g_lng, const float* __restrict__ g_lnb,
    const float* __restrict__ W1, const float* __restrict__ b1,
    const float* __restrict__ W2, const float* __restrict__ b2)
{
    extern __shared__ float sm[];
    float* Wq_s   = sm;                 // 4096
    float* Wih_s  = Wq_s + 4096;        // 12288
    float* Whh_s  = Wih_s + 12288;      // 12288
    float* W1_s   = Whh_s + 12288;      // 8192 (Wk during init)
    float* W2_s   = W1_s + 8192;        // 8192 (Wv during init)
    float* cc_s   = W2_s + 8192;        // 640
    float* ccp_s  = cc_s + 640;         // 640
    float* kk_s   = ccp_s + 640;        // 640
    float* lnx_s  = kk_s + 640;         // 640
    float* q_s    = lnx_s + 640;        // 640
    float* VW_s   = q_s + 640;          // 1920 ([m][192])
    float* gh_s   = VW_s + 1920;        // 1920 ([n][192])
    float* hh_s   = gh_s + 1920;        // 1280 ([n][128]); aliases vv during init
    float* attn_s = hh_s + 1280;        // 112 (100 used)
    float* mv_s   = attn_s + 112;       // 32 (20 used)
    float* vv_s   = hh_s;               // alias

    const int tid  = threadIdx.x;
    const int lane = tid & 31;
    const int wid  = tid >> 5;

    // async stage of the big iteration weights (group 0)
    stage_w_async(Wih, Wih_s, 192, 64, tid, TPB1);
    stage_w_async(Whh, Whh_s, 192, 64, tid, TPB1);
    asm volatile("cp.async.commit_group;\n" ::: "memory");

    // sync stage of the small init weights + cc
    stage_w(Wq, Wq_s, 64, 64, tid, TPB1);
    stage_w(Wk, W1_s, 64, 64, tid, TPB1);
    stage_w(Wv, W2_s, 64, 64, tid, TPB1);
    if (tid < 160) *reinterpret_cast<float4*>(cc_s + tid * 4) =
        *reinterpret_cast<const float4*>(cc0 + tid * 4);
    __syncthreads();

    // k, v : 128 rows x splitk4 (16 cols each), shuffle-combine in lane quads
    {
        int rid = tid >> 2, kp = tid & 3;
        float acc[NCL];
        const float* Wm = (rid < 64) ? W1_s : W2_s;
        int row = (rid < 64) ? rid : rid - 64;
        gemm_sc(Wm, cc_s, row, 64, kp * 16, 16, acc);
#pragma unroll
        for (int n = 0; n < NCL; n++) {
            acc[n] += __shfl_xor_sync(0xffffffffu, acc[n], 1);
            acc[n] += __shfl_xor_sync(0xffffffffu, acc[n], 2);
        }
        if (kp == 0) {
            float b = (rid < 64) ? bk[row] : bv[row];
            float* dst = (rid < 64) ? kk_s : vv_s;
#pragma unroll
            for (int n = 0; n < NCL; n++) dst[n * 64 + row] = acc[n] + b;
        }
    }
    __syncthreads();

    // stage W1/W2 async (group 1) — overwrites Wk/Wv areas (already consumed)
    stage_w_async(W1, W1_s, 128, 64, tid, TPB1);
    stage_w_async(W2, W2_s, 64, 128, tid, TPB1);
    asm volatile("cp.async.commit_group;\n" ::: "memory");
    asm volatile("cp.async.wait_group 1;\n" ::: "memory");  // Wih/Whh ready
    __syncthreads();

    // VW[m][r] = v[m] . Wih[r]  (iteration-invariant hoist), 192 rows x splitk2
    if (tid < 384) {
        int rid = tid >> 1, kp = tid & 1;
        float acc[NCL];
        gemm_sc(Wih_s, vv_s, rid, 64, kp * 32, 32, acc);
#pragma unroll
        for (int n = 0; n < NCL; n++)
            acc[n] += __shfl_xor_sync(0xffffffffu, acc[n], 1);
        if (kp == 0) {
#pragma unroll
            for (int n = 0; n < NCL; n++) VW_s[n * 192 + rid] = acc[n];
        }
    }
    asm volatile("cp.async.wait_group 0;\n" ::: "memory");  // W1/W2 ready
    __syncthreads();

    for (int it = 0; it < 3; ++it) {
        // ccp copy + LN1 stats (warp-per-row)
        ccp_s[tid] = cc_s[tid];
        if (tid < 128) ccp_s[512 + tid] = cc_s[512 + tid];
        if (wid < NCL) {
            float x0 = cc_s[wid * 64 + lane * 2];
            float x1 = cc_s[wid * 64 + lane * 2 + 1];
            float s = x0 + x1, q2 = x0 * x0 + x1 * x1;
#pragma unroll
            for (int o = 16; o; o >>= 1) {
                s  += __shfl_xor_sync(0xffffffffu, s, o);
                q2 += __shfl_xor_sync(0xffffffffu, q2, o);
            }
            if (lane == 0) {
                float m = s * (1.f / 64.f);
                mv_s[2 * wid] = m;
                mv_s[2 * wid + 1] = rsqrtf(q2 * (1.f / 64.f) - m * m + 1e-5f);
            }
        }
        __syncthreads();
        {
            int e = tid, n = e >> 6, i = e & 63;
            lnx_s[e] = (cc_s[e] - mv_s[2 * n]) * mv_s[2 * n + 1] * ccg[i] + ccb[i];
            if (tid < 128) {
                e = 512 + tid; n = e >> 6; i = e & 63;
                lnx_s[e] = (cc_s[e] - mv_s[2 * n]) * mv_s[2 * n + 1] * ccg[i] + ccb[i];
            }
        }
        __syncthreads();

        // stage A: 256 rows (q: 0-63 from lnx/Wq, gh: 64-255 from ccp/Whh) x splitk2
        {
            int rid = tid >> 1, kp = tid & 1;
            float acc[NCL];
            if (rid < 64) gemm_sc(Wq_s, lnx_s, rid, 64, kp * 32, 32, acc);
            else          gemm_sc(Whh_s, ccp_s, rid - 64, 64, kp * 32, 32, acc);
#pragma unroll
            for (int n = 0; n < NCL; n++)
                acc[n] += __shfl_xor_sync(0xffffffffu, acc[n], 1);
            if (kp == 0) {
                if (rid < 64) {
                    float b = bq[rid];
#pragma unroll
                    for (int n = 0; n < NCL; n++) q_s[n * 64 + rid] = acc[n] + b;
                } else {
                    int r = rid - 64;
                    float b = bhh[r];
#pragma unroll
                    for (int n = 0; n < NCL; n++) gh_s[n * 192 + r] = acc[n] + b;
                }
            }
        }
        __syncthreads();

        // logits: 100 dots x splitk4 (all threads compute w/ clamp, 400 write-eligible)
        {
            int nm = tid >> 2; if (nm > 99) nm = 99;
            int kp = tid & 3;
            int n = nm / 10, m = nm % 10;
            float s = 0.f;
            int c0 = kp * 16;
#pragma unroll
            for (int j = 0; j < 16; j++)
                s = fmaf(kk_s[n * 64 + c0 + j], q_s[m * 64 + c0 + j], s);
            s += __shfl_xor_sync(0xffffffffu, s, 1);
            s += __shfl_xor_sync(0xffffffffu, s, 2);
            if (tid < 400 && kp == 0) attn_s[n * 10 + m] = s * 0.125f;
        }
        __syncthreads();
        // softmax over axis 0 (+EPS)
        if (tid < NCL) {
            int m = tid;
            float a[NCL], mx = -1e30f;
#pragma unroll
            for (int n = 0; n < NCL; n++) { a[n] = attn_s[n * 10 + m]; mx = fmaxf(mx, a[n]); }
            float ss = 0.f;
#pragma unroll
            for (int n = 0; n < NCL; n++) { a[n] = __expf(a[n] - mx); ss += a[n]; }
            float inv = 1.f / ss;
#pragma unroll
            for (int n = 0; n < NCL; n++) attn_s[n * 10 + m] = a[n] * inv + 1e-8f;
        }
        __syncthreads();
        // renormalize over axis -1
        if (tid < NCL) {
            int n = tid;
            float ss = 0.f;
#pragma unroll
            for (int m = 0; m < NCL; m++) ss += attn_s[n * 10 + m];
            float inv = 1.f / ss;
#pragma unroll
            for (int m = 0; m < NCL; m++) attn_s[n * 10 + m] *= inv;
        }
        __syncthreads();

        // GRU (gi = attn @ VW + b_ih; gh precomputed)
        for (int e = tid; e < 640; e += TPB1) {
            int n = e >> 6, i = e & 63;
            float gi0 = bih[i], gi1 = bih[64 + i], gi2 = bih[128 + i];
#pragma unroll
            for (int m = 0; m < NCL; m++) {
                float a = attn_s[n * 10 + m];
                const float* vw = VW_s + m * 192;
                gi0 = fmaf(a, vw[i], gi0);
                gi1 = fmaf(a, vw[64 + i], gi1);
                gi2 = fmaf(a, vw[128 + i], gi2);
            }
            float h0 = gh_s[n * 192 + i];
            float h1 = gh_s[n * 192 + 64 + i];
            float h2 = gh_s[n * 192 + 128 + i];
            float r = fast_sigmoid(gi0 + h0);
            float z = fast_sigmoid(gi1 + h1);
            float nn = fast_tanh(gi2 + r * h2);
            cc_s[e] = (1.f - z) * nn + z * ccp_s[e];
        }
        __syncthreads();

        // LN2 stats + lnx
        if (wid < NCL) {
            float x0 = cc_s[wid * 64 + lane * 2];
            float x1 = cc_s[wid * 64 + lane * 2 + 1];
            float s = x0 + x1, q2 = x0 * x0 + x1 * x1;
#pragma unroll
            for (int o = 16; o; o >>= 1) {
                s  += __shfl_xor_sync(0xffffffffu, s, o);
                q2 += __shfl_xor_sync(0xffffffffu, q2, o);
            }
            if (lane == 0) {
                float m = s * (1.f / 64.f);
                mv_s[2 * wid] = m;
                mv_s[2 * wid + 1] = rsqrtf(q2 * (1.f / 64.f) - m * m + 1e-5f);
            }
        }
        __syncthreads();
        {
            int e = tid, n = e >> 6, i = e & 63;
            lnx_s[e] = (cc_s[e] - mv_s[2 * n]) * mv_s[2 * n + 1] * g_lng[i] + g_lnb[i];
            if (tid < 128) {
                e = 512 + tid; n = e >> 6; i = e & 63;
                lnx_s[e] = (cc_s[e] - mv_s[2 * n]) * mv_s[2 * n + 1] * g_lng[i] + g_lnb[i];
            }
        }
        __syncthreads();

        // MLP1: 128 rows x splitk4
        {
            int rid = tid >> 2, kp = tid & 3;
            float acc[NCL];
            gemm_sc(W1_s, lnx_s, rid, 64, kp * 16, 16, acc);
#pragma unroll
            for (int n = 0; n < NCL; n++) {
                acc[n] += __shfl_xor_sync(0xffffffffu, acc[n], 1);
                acc[n] += __shfl_xor_sync(0xffffffffu, acc[n], 2);
            }
            if (kp == 0) {
                float b = b1[rid];
#pragma unroll
                for (int n = 0; n < NCL; n++)
                    hh_s[n * 128 + rid] = fmaxf(acc[n] + b, 0.f);
            }
        }
        __syncthreads();
        // MLP2 + residual: 64 rows (L=128) x splitk8
        {
            int rid = tid >> 3, kp = tid & 7;
            float acc[NCL];
            gemm_sc(W2_s, hh_s, rid, 128, kp * 16, 16, acc);
#pragma unroll
            for (int n = 0; n < NCL; n++) {
                acc[n] += __shfl_xor_sync(0xffffffffu, acc[n], 1);
                acc[n] += __shfl_xor_sync(0xffffffffu, acc[n], 2);
                acc[n] += __shfl_xor_sync(0xffffffffu, acc[n], 4);
            }
            if (kp == 0) {
                float b = b2[rid];
#pragma unroll
                for (int n = 0; n < NCL; n++)
                    cc_s[n * 64 + rid] += acc[n] + b;
            }
        }
        __syncthreads();
    }

    // write ALL 640 elements
    g_cc[tid] = cc_s[tid];
    if (tid < 128) g_cc[512 + tid] = cc_s[512 + tid];
}

// ---------------- kernel 2: per-slot MLP + max (4096 blocks) — R1 proven ----------------

__global__ void __launch_bounds__(64) slot_kernel(
    const float* __restrict__ Wa, const float* __restrict__ ba,
    const float* __restrict__ Wb, const float* __restrict__ bb,
    float* __restrict__ out)
{
    __shared__ float bufA[4096];
    __shared__ float bufB[4096];
    __shared__ float cc2[640];
    __shared__ float hsm[640];

    const int s = blockIdx.x;
    const int t = threadIdx.x;
    const float* wa = Wa + (size_t)s * 4096;
    const float* wb = Wb + (size_t)s * 4096;

    // double-buffered streaming loads (swizzled dst), Wb in flight during phase 1
#pragma unroll
    for (int k = 0; k < 16; ++k) {
        int e = (t + 64 * k) * 4;
        int r = e >> 6, c = e & 63;
        cp_async16(&bufA[r * 64 + (c ^ ((r << 2) & 60))], wa + e);
    }
    asm volatile("cp.async.commit_group;\n" ::: "memory");
#pragma unroll
    for (int k = 0; k < 16; ++k) {
        int e = (t + 64 * k) * 4;
        int r = e >> 6, c = e & 63;
        cp_async16(&bufB[r * 64 + (c ^ ((r << 2) & 60))], wb + e);
    }
    asm volatile("cp.async.commit_group;\n" ::: "memory");

    for (int e = t; e < 640; e += 64) cc2[e] = g_cc[e];

    asm volatile("cp.async.wait_group 1;\n" ::: "memory");
    __syncthreads();

    float acc[NCL];
    // h[n][t] = relu(Wa[t] . cc[n] + ba[s][t])
    gemm_sc(bufA, cc2, t, 64, 0, 64, acc);
    {
        float b = ba[s * 64 + t];
#pragma unroll
        for (int n = 0; n < NCL; n++) hsm[n * 64 + t] = fmaxf(acc[n] + b, 0.f);
    }

    asm volatile("cp.async.wait_group 0;\n" ::: "memory");
    __syncthreads();

    // out[n][t] = Wb[t] . h[n] + bb[s][t]; max over n
    gemm_sc(bufB, hsm, t, 64, 0, 64, acc);
    float b = bb[s * 64 + t];
    float m = -3.4e38f;
#pragma unroll
    for (int n = 0; n < NCL; n++) m = fmaxf(m, acc[n] + b);
    out[s * 64 + t] = m;
}

// ---------------- launch ----------------

extern "C" void kernel_launch(void* const* d_in, const int* in_sizes, int n_in,
                              void* d_out, int out_size) {
    const float* cc0 = (const float*)d_in[0];
    const float* Wk  = (const float*)d_in[1];
    const float* bk  = (const float*)d_in[2];
    const float* Wq  = (const float*)d_in[3];
    const float* bq  = (const float*)d_in[4];
    const float* Wv  = (const float*)d_in[5];
    const float* bv  = (const float*)d_in[6];
    const float* ccg = (const float*)d_in[7];
    const float* ccb = (const float*)d_in[8];
    const float* Wih = (const float*)d_in[9];
    const float* Whh = (const float*)d_in[10];
    const float* bih = (const float*)d_in[11];
    const float* bhh = (const float*)d_in[12];
    const float* lng = (const float*)d_in[13];
    const float* lnb = (const float*)d_in[14];
    const float* W1  = (const float*)d_in[15];
    const float* b1  = (const float*)d_in[16];
    const float* W2  = (const float*)d_in[17];
    const float* b2  = (const float*)d_in[18];
    const float* Wa  = (const float*)d_in[19];
    const float* ba  = (const float*)d_in[20];
    const float* Wb  = (const float*)d_in[21];
    const float* bb  = (const float*)d_in[22];
    float* out = (float*)d_out;

    constexpr int SMEM1 = 53520 * 4;  // 214,080 B < 227 KB opt-in
    cudaFuncSetAttribute(iter_kernel, cudaFuncAttributeMaxDynamicSharedMemorySize, SMEM1);

    iter_kernel<<<1, TPB1, SMEM1>>>(cc0, Wk, bk, Wq, bq, Wv, bv, ccg, ccb,
                                    Wih, Whh, bih, bhh, lng, lnb, W1, b1, W2, b2);
    slot_kernel<<<4096, 64>>>(Wa, ba, Wb, bb, out);
}

// round 7
// speedup vs baseline: 1.5323x; 1.0030x over previous
#include <cuda_runtime.h>
#include <cuda_bf16.h>
#include <math.h>

#define NCL 10
#define DD 64
#define TPB1 512
#define PRE_BLOCKS 1024   // blocks 1..1024 of phase1 prefetch Wa/Wb into L2

// final cluster centers from the iterative part
__device__ float g_cc[NCL * DD];
__device__ float g_sink;   // keeps prefetch loads alive; never meaningfully written

// ---------------- helpers ----------------

__device__ __forceinline__ float fast_sigmoid(float x) {
    return 1.f / (1.f + __expf(-x));
}
__device__ __forceinline__ float fast_tanh(float x) {
    return 1.f - 2.f / (1.f + __expf(2.f * x));   // stable at both tails
}

__device__ __forceinline__ void cp_async16(float* smem_dst, const float* gsrc) {
    unsigned d = (unsigned)__cvta_generic_to_shared(smem_dst);
    asm volatile("cp.async.cg.shared.global [%0], [%1], 16;\n" :: "r"(d), "l"(gsrc));
}

// XOR swizzle: (r, c) -> r*L + (c ^ ((r<<2) & (L-4))). float4-preserving,
// conflict-free LDS.128 when lanes read consecutive rows.
__device__ __forceinline__ void stage_w(const float* __restrict__ g, float* __restrict__ s,
                                        int R, int L, int tid, int T) {
    int total4 = (R * L) >> 2;
    for (int e4 = tid; e4 < total4; e4 += T) {
        int e = e4 << 2;
        int r = e / L;
        int c = e & (L - 1);
        float4 v = *reinterpret_cast<const float4*>(g + e);
        *reinterpret_cast<float4*>(s + r * L + (c ^ ((r << 2) & (L - 4)))) = v;
    }
}

__device__ __forceinline__ void stage_w_async(const float* __restrict__ g, float* __restrict__ s,
                                              int R, int L, int tid, int T) {
    int total4 = (R * L) >> 2;
    for (int e4 = tid; e4 < total4; e4 += T) {
        int e = e4 << 2;
        int r = e / L;
        int c = e & (L - 1);
        cp_async16(s + r * L + (c ^ ((r << 2) & (L - 4))), g + e);
    }
}

// scalar gemm over a column subrange: acc[n] = sum_{c in [c0,c0+nc)} W[r][c]*act[n*L+c]
// One weight LDS.128 feeds 40 FFMAs; act reads are warp broadcasts.
__device__ __forceinline__ void gemm_sc(const float* __restrict__ Wsm,
                                        const float* __restrict__ act,
                                        int r, int L, int c0, int nc, float* acc) {
#pragma unroll
    for (int n = 0; n < NCL; n++) acc[n] = 0.f;
    const int sw = (r << 2) & (L - 4);
    const float* wrow = Wsm + r * L;
#pragma unroll 4
    for (int c = c0; c < c0 + nc; c += 4) {
        float4 w = *reinterpret_cast<const float4*>(wrow + (c ^ sw));
#pragma unroll
        for (int n = 0; n < NCL; n++) {
            float4 a = *reinterpret_cast<const float4*>(act + n * L + c);
            acc[n] = fmaf(w.x, a.x, acc[n]);
            acc[n] = fmaf(w.y, a.y, acc[n]);
            acc[n] = fmaf(w.z, a.z, acc[n]);
            acc[n] = fmaf(w.w, a.w, acc[n]);
        }
    }
}

// ---------------- phase 1: block 0 = iterative slot attention; blocks 1.. = L2 prefetch ----------------

__global__ void __launch_bounds__(TPB1) phase1_kernel(
    const float* __restrict__ cc0,
    const float* __restrict__ Wk, const float* __restrict__ bk,
    const float* __restrict__ Wq, const float* __restrict__ bq,
    const float* __restrict__ Wv, const float* __restrict__ bv,
    const float* __restrict__ ccg, const float* __restrict__ ccb,
    const float* __restrict__ Wih, const float* __restrict__ Whh,
    const float* __restrict__ bih, const float* __restrict__ bhh,
    const float* __restrict__ g_lng, const float* __restrict__ g_lnb,
    const float* __restrict__ W1, const float* __restrict__ b1,
    const float* __restrict__ W2, const float* __restrict__ b2,
    const float* __restrict__ Wa, const float* __restrict__ Wb)
{
    extern __shared__ float sm[];

    // ---- prefetch blocks: stream Wa/Wb through L2, then exit ----
    if (blockIdx.x != 0) {
        int pid = blockIdx.x - 1;                       // 0..PRE_BLOCKS-1
        const float4* a4 = reinterpret_cast<const float4*>(Wa);
        const float4* b4 = reinterpret_cast<const float4*>(Wb);
        long base = (long)pid * TPB1 + threadIdx.x;     // 524288 threads total
        const long stride = (long)PRE_BLOCKS * TPB1;
        float s = 0.f;
#pragma unroll
        for (int j = 0; j < 8; j++) {                   // 8 x 524288 = 4M float4 each
            float4 va = a4[base + j * stride];
            float4 vb = b4[base + j * stride];
            s += va.x + va.y + va.z + va.w + vb.x + vb.y + vb.z + vb.w;
        }
        if (s == 1234567.25f) g_sink = s;               // unprovable -> loads kept
        return;
    }

    // ---- block 0: iterative core (identical to R6 iter_kernel) ----
    float* Wq_s   = sm;                 // 4096
    float* Wih_s  = Wq_s + 4096;        // 12288
    float* Whh_s  = Wih_s + 12288;      // 12288
    float* W1_s   = Whh_s + 12288;      // 8192 (Wk during init)
    float* W2_s   = W1_s + 8192;        // 8192 (Wv during init)
    float* cc_s   = W2_s + 8192;        // 640
    float* ccp_s  = cc_s + 640;         // 640
    float* kk_s   = ccp_s + 640;        // 640
    float* lnx_s  = kk_s + 640;         // 640
    float* q_s    = lnx_s + 640;        // 640
    float* VW_s   = q_s + 640;          // 1920 ([m][192])
    float* gh_s   = VW_s + 1920;        // 1920 ([n][192])
    float* hh_s   = gh_s + 1920;        // 1280 ([n][128]); aliases vv during init
    float* attn_s = hh_s + 1280;        // 112 (100 used)
    float* mv_s   = attn_s + 112;       // 32 (20 used)
    float* vv_s   = hh_s;               // alias

    const int tid  = threadIdx.x;
    const int lane = tid & 31;
    const int wid  = tid >> 5;

    // async stage of the big iteration weights (group 0)
    stage_w_async(Wih, Wih_s, 192, 64, tid, TPB1);
    stage_w_async(Whh, Whh_s, 192, 64, tid, TPB1);
    asm volatile("cp.async.commit_group;\n" ::: "memory");

    // sync stage of the small init weights + cc
    stage_w(Wq, Wq_s, 64, 64, tid, TPB1);
    stage_w(Wk, W1_s, 64, 64, tid, TPB1);
    stage_w(Wv, W2_s, 64, 64, tid, TPB1);
    if (tid < 160) *reinterpret_cast<float4*>(cc_s + tid * 4) =
        *reinterpret_cast<const float4*>(cc0 + tid * 4);
    __syncthreads();

    // k, v : 128 rows x splitk4 (16 cols each), shuffle-combine in lane quads
    {
        int rid = tid >> 2, kp = tid & 3;
        float acc[NCL];
        const float* Wm = (rid < 64) ? W1_s : W2_s;
        int row = (rid < 64) ? rid : rid - 64;
        gemm_sc(Wm, cc_s, row, 64, kp * 16, 16, acc);
#pragma unroll
        for (int n = 0; n < NCL; n++) {
            acc[n] += __shfl_xor_sync(0xffffffffu, acc[n], 1);
            acc[n] += __shfl_xor_sync(0xffffffffu, acc[n], 2);
        }
        if (kp == 0) {
            float b = (rid < 64) ? bk[row] : bv[row];
            float* dst = (rid < 64) ? kk_s : vv_s;
#pragma unroll
            for (int n = 0; n < NCL; n++) dst[n * 64 + row] = acc[n] + b;
        }
    }
    __syncthreads();

    // stage W1/W2 async (group 1) — overwrites Wk/Wv areas (already consumed)
    stage_w_async(W1, W1_s, 128, 64, tid, TPB1);
    stage_w_async(W2, W2_s, 64, 128, tid, TPB1);
    asm volatile("cp.async.commit_group;\n" ::: "memory");
    asm volatile("cp.async.wait_group 1;\n" ::: "memory");  // Wih/Whh ready
    __syncthreads();

    // VW[m][r] = v[m] . Wih[r]  (iteration-invariant hoist), 192 rows x splitk2
    if (tid < 384) {
        int rid = tid >> 1, kp = tid & 1;
        float acc[NCL];
        gemm_sc(Wih_s, vv_s, rid, 64, kp * 32, 32, acc);
#pragma unroll
        for (int n = 0; n < NCL; n++)
            acc[n] += __shfl_xor_sync(0xffffffffu, acc[n], 1);
        if (kp == 0) {
#pragma unroll
            for (int n = 0; n < NCL; n++) VW_s[n * 192 + rid] = acc[n];
        }
    }
    asm volatile("cp.async.wait_group 0;\n" ::: "memory");  // W1/W2 ready
    __syncthreads();

    for (int it = 0; it < 3; ++it) {
        // ccp copy + LN1 stats (warp-per-row)
        ccp_s[tid] = cc_s[tid];
        if (tid < 128) ccp_s[512 + tid] = cc_s[512 + tid];
        if (wid < NCL) {
            float x0 = cc_s[wid * 64 + lane * 2];
            float x1 = cc_s[wid * 64 + lane * 2 + 1];
            float s = x0 + x1, q2 = x0 * x0 + x1 * x1;
#pragma unroll
            for (int o = 16; o; o >>= 1) {
                s  += __shfl_xor_sync(0xffffffffu, s, o);
                q2 += __shfl_xor_sync(0xffffffffu, q2, o);
            }
            if (lane == 0) {
                float m = s * (1.f / 64.f);
                mv_s[2 * wid] = m;
                mv_s[2 * wid + 1] = rsqrtf(q2 * (1.f / 64.f) - m * m + 1e-5f);
            }
        }
        __syncthreads();
        {
            int e = tid, n = e >> 6, i = e & 63;
            lnx_s[e] = (cc_s[e] - mv_s[2 * n]) * mv_s[2 * n + 1] * ccg[i] + ccb[i];
            if (tid < 128) {
                e = 512 + tid; n = e >> 6; i = e & 63;
                lnx_s[e] = (cc_s[e] - mv_s[2 * n]) * mv_s[2 * n + 1] * ccg[i] + ccb[i];
            }
        }
        __syncthreads();

        // stage A: 256 rows (q: 0-63 from lnx/Wq, gh: 64-255 from ccp/Whh) x splitk2
        {
            int rid = tid >> 1, kp = tid & 1;
            float acc[NCL];
            if (rid < 64) gemm_sc(Wq_s, lnx_s, rid, 64, kp * 32, 32, acc);
            else          gemm_sc(Whh_s, ccp_s, rid - 64, 64, kp * 32, 32, acc);
#pragma unroll
            for (int n = 0; n < NCL; n++)
                acc[n] += __shfl_xor_sync(0xffffffffu, acc[n], 1);
            if (kp == 0) {
                if (rid < 64) {
                    float b = bq[rid];
#pragma unroll
                    for (int n = 0; n < NCL; n++) q_s[n * 64 + rid] = acc[n] + b;
                } else {
                    int r = rid - 64;
                    float b = bhh[r];
#pragma unroll
                    for (int n = 0; n < NCL; n++) gh_s[n * 192 + r] = acc[n] + b;
                }
            }
        }
        __syncthreads();

        // logits: 100 dots x splitk4
        {
            int nm = tid >> 2; if (nm > 99) nm = 99;
            int kp = tid & 3;
            int n = nm / 10, m = nm % 10;
            float s = 0.f;
            int c0 = kp * 16;
#pragma unroll
            for (int j = 0; j < 16; j++)
                s = fmaf(kk_s[n * 64 + c0 + j], q_s[m * 64 + c0 + j], s);
            s += __shfl_xor_sync(0xffffffffu, s, 1);
            s += __shfl_xor_sync(0xffffffffu, s, 2);
            if (tid < 400 && kp == 0) attn_s[n * 10 + m] = s * 0.125f;
        }
        __syncthreads();
        // softmax over axis 0 (+EPS)
        if (tid < NCL) {
            int m = tid;
            float a[NCL], mx = -1e30f;
#pragma unroll
            for (int n = 0; n < NCL; n++) { a[n] = attn_s[n * 10 + m]; mx = fmaxf(mx, a[n]); }
            float ss = 0.f;
#pragma unroll
            for (int n = 0; n < NCL; n++) { a[n] = __expf(a[n] - mx); ss += a[n]; }
            float inv = 1.f / ss;
#pragma unroll
            for (int n = 0; n < NCL; n++) attn_s[n * 10 + m] = a[n] * inv + 1e-8f;
        }
        __syncthreads();
        // renormalize over axis -1
        if (tid < NCL) {
            int n = tid;
            float ss = 0.f;
#pragma unroll
            for (int m = 0; m < NCL; m++) ss += attn_s[n * 10 + m];
            float inv = 1.f / ss;
#pragma unroll
            for (int m = 0; m < NCL; m++) attn_s[n * 10 + m] *= inv;
        }
        __syncthreads();

        // GRU (gi = attn @ VW + b_ih; gh precomputed)
        for (int e = tid; e < 640; e += TPB1) {
            int n = e >> 6, i = e & 63;
            float gi0 = bih[i], gi1 = bih[64 + i], gi2 = bih[128 + i];
#pragma unroll
            for (int m = 0; m < NCL; m++) {
                float a = attn_s[n * 10 + m];
                const float* vw = VW_s + m * 192;
                gi0 = fmaf(a, vw[i], gi0);
                gi1 = fmaf(a, vw[64 + i], gi1);
                gi2 = fmaf(a, vw[128 + i], gi2);
            }
            float h0 = gh_s[n * 192 + i];
            float h1 = gh_s[n * 192 + 64 + i];
            float h2 = gh_s[n * 192 + 128 + i];
            float r = fast_sigmoid(gi0 + h0);
            float z = fast_sigmoid(gi1 + h1);
            float nn = fast_tanh(gi2 + r * h2);
            cc_s[e] = (1.f - z) * nn + z * ccp_s[e];
        }
        __syncthreads();

        // LN2 stats + lnx
        if (wid < NCL) {
            float x0 = cc_s[wid * 64 + lane * 2];
            float x1 = cc_s[wid * 64 + lane * 2 + 1];
            float s = x0 + x1, q2 = x0 * x0 + x1 * x1;
#pragma unroll
            for (int o = 16; o; o >>= 1) {
                s  += __shfl_xor_sync(0xffffffffu, s, o);
                q2 += __shfl_xor_sync(0xffffffffu, q2, o);
            }
            if (lane == 0) {
                float m = s * (1.f / 64.f);
                mv_s[2 * wid] = m;
                mv_s[2 * wid + 1] = rsqrtf(q2 * (1.f / 64.f) - m * m + 1e-5f);
            }
        }
        __syncthreads();
        {
            int e = tid, n = e >> 6, i = e & 63;
            lnx_s[e] = (cc_s[e] - mv_s[2 * n]) * mv_s[2 * n + 1] * g_lng[i] + g_lnb[i];
            if (tid < 128) {
                e = 512 + tid; n = e >> 6; i = e & 63;
                lnx_s[e] = (cc_s[e] - mv_s[2 * n]) * mv_s[2 * n + 1] * g_lng[i] + g_lnb[i];
            }
        }
        __syncthreads();

        // MLP1: 128 rows x splitk4
        {
            int rid = tid >> 2, kp = tid & 3;
            float acc[NCL];
            gemm_sc(W1_s, lnx_s, rid, 64, kp * 16, 16, acc);
#pragma unroll
            for (int n = 0; n < NCL; n++) {
                acc[n] += __shfl_xor_sync(0xffffffffu, acc[n], 1);
                acc[n] += __shfl_xor_sync(0xffffffffu, acc[n], 2);
            }
            if (kp == 0) {
                float b = b1[rid];
#pragma unroll
                for (int n = 0; n < NCL; n++)
                    hh_s[n * 128 + rid] = fmaxf(acc[n] + b, 0.f);
            }
        }
        __syncthreads();
        // MLP2 + residual: 64 rows (L=128) x splitk8
        {
            int rid = tid >> 3, kp = tid & 7;
            float acc[NCL];
            gemm_sc(W2_s, hh_s, rid, 128, kp * 16, 16, acc);
#pragma unroll
            for (int n = 0; n < NCL; n++) {
                acc[n] += __shfl_xor_sync(0xffffffffu, acc[n], 1);
                acc[n] += __shfl_xor_sync(0xffffffffu, acc[n], 2);
                acc[n] += __shfl_xor_sync(0xffffffffu, acc[n], 4);
            }
            if (kp == 0) {
                float b = b2[rid];
#pragma unroll
                for (int n = 0; n < NCL; n++)
                    cc_s[n * 64 + rid] += acc[n] + b;
            }
        }
        __syncthreads();
    }

    // write ALL 640 elements
    g_cc[tid] = cc_s[tid];
    if (tid < 128) g_cc[512 + tid] = cc_s[512 + tid];
}

// ---------------- kernel 2: per-slot MLP + max (4096 blocks) — weights now L2-hot ----------------

__global__ void __launch_bounds__(64) slot_kernel(
    const float* __restrict__ Wa, const float* __restrict__ ba,
    const float* __restrict__ Wb, const float* __restrict__ bb,
    float* __restrict__ out)
{
    __shared__ float bufA[4096];
    __shared__ float bufB[4096];
    __shared__ float cc2[640];
    __shared__ float hsm[640];

    const int s = blockIdx.x;
    const int t = threadIdx.x;
    const float* wa = Wa + (size_t)s * 4096;
    const float* wb = Wb + (size_t)s * 4096;

    // double-buffered streaming loads (swizzled dst), Wb in flight during phase 1
#pragma unroll
    for (int k = 0; k < 16; ++k) {
        int e = (t + 64 * k) * 4;
        int r = e >> 6, c = e & 63;
        cp_async16(&bufA[r * 64 + (c ^ ((r << 2) & 60))], wa + e);
    }
    asm volatile("cp.async.commit_group;\n" ::: "memory");
#pragma unroll
    for (int k = 0; k < 16; ++k) {
        int e = (t + 64 * k) * 4;
        int r = e >> 6, c = e & 63;
        cp_async16(&bufB[r * 64 + (c ^ ((r << 2) & 60))], wb + e);
    }
    asm volatile("cp.async.commit_group;\n" ::: "memory");

    for (int e = t; e < 640; e += 64) cc2[e] = g_cc[e];

    asm volatile("cp.async.wait_group 1;\n" ::: "memory");
    __syncthreads();

    float acc[NCL];
    // h[n][t] = relu(Wa[t] . cc[n] + ba[s][t])
    gemm_sc(bufA, cc2, t, 64, 0, 64, acc);
    {
        float b = ba[s * 64 + t];
#pragma unroll
        for (int n = 0; n < NCL; n++) hsm[n * 64 + t] = fmaxf(acc[n] + b, 0.f);
    }

    asm volatile("cp.async.wait_group 0;\n" ::: "memory");
    __syncthreads();

    // out[n][t] = Wb[t] . h[n] + bb[s][t]; max over n
    gemm_sc(bufB, hsm, t, 64, 0, 64, acc);
    float b = bb[s * 64 + t];
    float m = -3.4e38f;
#pragma unroll
    for (int n = 0; n < NCL; n++) m = fmaxf(m, acc[n] + b);
    out[s * 64 + t] = m;
}

// ---------------- launch ----------------

extern "C" void kernel_launch(void* const* d_in, const int* in_sizes, int n_in,
                              void* d_out, int out_size) {
    const float* cc0 = (const float*)d_in[0];
    const float* Wk  = (const float*)d_in[1];
    const float* bk  = (const float*)d_in[2];
    const float* Wq  = (const float*)d_in[3];
    const float* bq  = (const float*)d_in[4];
    const float* Wv  = (const float*)d_in[5];
    const float* bv  = (const float*)d_in[6];
    const float* ccg = (const float*)d_in[7];
    const float* ccb = (const float*)d_in[8];
    const float* Wih = (const float*)d_in[9];
    const float* Whh = (const float*)d_in[10];
    const float* bih = (const float*)d_in[11];
    const float* bhh = (const float*)d_in[12];
    const float* lng = (const float*)d_in[13];
    const float* lnb = (const float*)d_in[14];
    const float* W1  = (const float*)d_in[15];
    const float* b1  = (const float*)d_in[16];
    const float* W2  = (const float*)d_in[17];
    const float* b2  = (const float*)d_in[18];
    const float* Wa  = (const float*)d_in[19];
    const float* ba  = (const float*)d_in[20];
    const float* Wb  = (const float*)d_in[21];
    const float* bb  = (const float*)d_in[22];
    float* out = (float*)d_out;

    constexpr int SMEM1 = 53520 * 4;  // 214,080 B < 227 KB opt-in
    cudaFuncSetAttribute(phase1_kernel, cudaFuncAttributeMaxDynamicSharedMemorySize, SMEM1);

    // block 0: iterative core; blocks 1..PRE_BLOCKS: pull Wa/Wb into L2 concurrently
    phase1_kernel<<<1 + PRE_BLOCKS, TPB1, SMEM1>>>(cc0, Wk, bk, Wq, bq, Wv, bv, ccg, ccb,
                                                   Wih, Whh, bih, bhh, lng, lnb, W1, b1, W2, b2,
                                                   Wa, Wb);
    slot_kernel<<<4096, 64>>>(Wa, ba, Wb, bb, out);
}